// round 1
// baseline (speedup 1.0000x reference)
#include <cuda_runtime.h>
#include <math.h>

// BM3D-deblurring (RI filter + global empirical Wiener), fully in-Fourier.
// Pipeline (all fp32):
//   P(scatter psf, circular roll) -> Hf = fft2(P) -> ri, psd
//   Z = fft2(y);  per-element: z*=ri; S=max(|z|^2/n - psd,0); z*=S/(S+psd+eps)
//   out = real(ifft2(z))
// Custom radix-2 shared-memory 1024-pt FFTs; column pass fuses fwd-FFT,
// pointwise Wiener, and inv-FFT in one kernel (single global round trip).

#define NPT   1024
#define LOGN  10
#define HWPIX (1u << 20)
#define MAXIMG 24

static __device__ float2 g_Z[(size_t)MAXIMG << 20]; // 192 MB scratch spectra
static __device__ float2 g_P[1u << 20];             // OTF scratch
static __device__ float2 g_RI[1u << 20];            // regularized inverse filter
static __device__ float  g_PSD[1u << 20];           // colored-noise PSD
static __device__ float2 g_tw[512];                 // twiddles W_1024^k, k<512

__device__ __forceinline__ int brev10(int i) { return (int)(__brev((unsigned)i) >> 22); }

// One radix-2 DIT butterfly for butterfly-index j (0..511) at stage st (1..10).
// s must hold bit-reversed input before stage 1; output is natural order.
__device__ __forceinline__ void butterfly(float2* s, int j, int st, bool inv) {
    int half = 1 << (st - 1);
    int p  = j & (half - 1);
    int i1 = ((j >> (st - 1)) << st) + p;
    int i2 = i1 + half;
    float2 w = g_tw[p << (LOGN - st)];
    float wy = inv ? -w.y : w.y;
    float2 b = s[i2];
    float tr = w.x * b.x - wy * b.y;
    float ti = w.x * b.y + wy * b.x;
    float2 a = s[i1];
    s[i1] = make_float2(a.x + tr, a.y + ti);
    s[i2] = make_float2(a.x - tr, a.y - ti);
}

// ---------------- init: twiddles + circularly-rolled PSF ----------------
__global__ void k_init(const float* __restrict__ psf, int kh) {
    int idx = blockIdx.x * 256 + threadIdx.x;           // 0 .. 2^20-1
    int r = idx >> 10, c = idx & 1023;
    int i = (r + (kh >> 1)) & 1023;
    int j = (c + (kh >> 1)) & 1023;
    float v = (i < kh && j < kh) ? psf[i * kh + j] : 0.f;
    g_P[idx] = make_float2(v, 0.f);
    if (idx < 512) {
        float sn, cs;
        sincospif(-(float)idx / 512.0f, &sn, &cs);      // exp(-2*pi*i*idx/1024)
        g_tw[idx] = make_float2(cs, sn);
    }
}

// ---------------- compute RI filter and PSD from Hf (= fft2(P)) ---------
__global__ void k_ri() {
    int idx = blockIdx.x * 256 + threadIdx.x;
    float2 h = g_P[idx];
    float d = h.x * h.x + h.y * h.y + 0.0025f;          // |H|^2 + sigma^2
    float inv = 1.0f / d;
    float rx = h.x * inv, ry = -h.y * inv;              // conj(H)/(|H|^2+s^2)
    g_RI[idx]  = make_float2(rx, ry);
    g_PSD[idx] = 0.0025f * (rx * rx + ry * ry) * 1048576.0f;
}

// ---------------- row FFT, real input (y) -> g_Z ------------------------
__global__ void __launch_bounds__(256) k_row_fwd_real(const float* __restrict__ y) {
    __shared__ float2 s[NPT];
    int tid = threadIdx.x;
    size_t base = (((size_t)blockIdx.y) << 20) + ((size_t)blockIdx.x << 10);
    #pragma unroll
    for (int l = tid; l < NPT; l += 256)
        s[brev10(l)] = make_float2(y[base + l], 0.f);
    __syncthreads();
    #pragma unroll
    for (int st = 1; st <= LOGN; ++st) {
        butterfly(s, tid, st, false);
        butterfly(s, tid + 256, st, false);
        __syncthreads();
    }
    #pragma unroll
    for (int l = tid; l < NPT; l += 256) g_Z[base + l] = s[l];
}

// ---------------- row FFT, complex in-place on g_P ----------------------
__global__ void __launch_bounds__(256) k_row_fwd_P() {
    __shared__ float2 s[NPT];
    int tid = threadIdx.x;
    size_t base = (size_t)blockIdx.x << 10;
    #pragma unroll
    for (int l = tid; l < NPT; l += 256) s[brev10(l)] = g_P[base + l];
    __syncthreads();
    #pragma unroll
    for (int st = 1; st <= LOGN; ++st) {
        butterfly(s, tid, st, false);
        butterfly(s, tid + 256, st, false);
        __syncthreads();
    }
    #pragma unroll
    for (int l = tid; l < NPT; l += 256) g_P[base + l] = s[l];
}

// ---------------- row inverse FFT + real output -------------------------
__global__ void __launch_bounds__(256) k_row_inv_out(float* __restrict__ out) {
    __shared__ float2 s[NPT];
    int tid = threadIdx.x;
    size_t base = (((size_t)blockIdx.y) << 20) + ((size_t)blockIdx.x << 10);
    #pragma unroll
    for (int l = tid; l < NPT; l += 256) s[brev10(l)] = g_Z[base + l];
    __syncthreads();
    #pragma unroll
    for (int st = 1; st <= LOGN; ++st) {
        butterfly(s, tid, st, true);
        butterfly(s, tid + 256, st, true);
        __syncthreads();
    }
    const float scale = 1.0f / 1048576.0f;              // 1/(H*W) ifft2 norm
    #pragma unroll
    for (int l = tid; l < NPT; l += 256) out[base + l] = s[l].x * scale;
}

// ---------------- column pass: fwd FFT [, Wiener, inv FFT] --------------
// 4 columns per block, stride-padded SMEM. WIENER=1: fuse ri-multiply +
// empirical Wiener shrink + inverse column FFT (saves 2 global passes).
template <int WIENER>
__global__ void __launch_bounds__(256) k_col() {
    float2* buf = WIENER ? g_Z : g_P;
    __shared__ float2 sm[4 * 1025];
    int tid = threadIdx.x;
    int c0  = blockIdx.x * 4;
    size_t base = (((size_t)blockIdx.y) << 20) + (size_t)c0;

    #pragma unroll
    for (int l = tid; l < 4096; l += 256) {
        int c = l & 3, r = l >> 2;
        sm[c * 1025 + brev10(r)] = buf[base + ((size_t)r << 10) + c];
    }
    __syncthreads();
    #pragma unroll
    for (int st = 1; st <= LOGN; ++st) {
        #pragma unroll
        for (int b = 0; b < 8; ++b) {
            int idx = tid + b * 256;
            butterfly(sm + (idx >> 9) * 1025, idx & 511, st, false);
        }
        __syncthreads();
    }
    if (WIENER) {
        const float inv_n = 1.0f / 1048576.0f;
        #pragma unroll
        for (int l = tid; l < 4096; l += 256) {
            int c = l & 3, u = l >> 2;
            int gi = (u << 10) + c0 + c;
            float2 z  = sm[c * 1025 + u];
            float2 ri = g_RI[gi];
            float zr = z.x * ri.x - z.y * ri.y;
            float zi = z.x * ri.y + z.y * ri.x;
            float p = g_PSD[gi];
            float S = fmaxf((zr * zr + zi * zi) * inv_n - p, 0.0f);
            float w = S / (S + p + 1e-12f);
            sm[c * 1025 + u] = make_float2(zr * w, zi * w);
        }
        __syncthreads();
        // bit-reversal permutation (DIT inverse needs bit-reversed input)
        #pragma unroll
        for (int l = tid; l < 4096; l += 256) {
            int c = l & 3, r = l >> 2;
            int j = brev10(r);
            if (j > r) {
                float2 t = sm[c * 1025 + r];
                sm[c * 1025 + r] = sm[c * 1025 + j];
                sm[c * 1025 + j] = t;
            }
        }
        __syncthreads();
        #pragma unroll
        for (int st = 1; st <= LOGN; ++st) {
            #pragma unroll
            for (int b = 0; b < 8; ++b) {
                int idx = tid + b * 256;
                butterfly(sm + (idx >> 9) * 1025, idx & 511, st, true);
            }
            __syncthreads();
        }
    }
    #pragma unroll
    for (int l = tid; l < 4096; l += 256) {
        int c = l & 3, r = l >> 2;
        buf[base + ((size_t)r << 10) + c] = sm[c * 1025 + r];
    }
}

extern "C" void kernel_launch(void* const* d_in, const int* in_sizes, int n_in,
                              void* d_out, int out_size) {
    const float* y   = (const float*)d_in[0];
    const float* psf = (const float*)d_in[1];
    float* out = (float*)d_out;

    int imgs = in_sizes[0] >> 20;             // 8*3 = 24 images of 1024x1024
    if (imgs > MAXIMG) imgs = MAXIMG;
    int kh = (int)lroundf(sqrtf((float)in_sizes[1]));   // 25

    // PSF -> OTF -> RI filter + PSD
    k_init<<<4096, 256>>>(psf, kh);
    k_row_fwd_P<<<1024, 256>>>();
    k_col<0><<<dim3(256, 1), 256>>>();
    k_ri<<<4096, 256>>>();

    // Main pipeline: fwd row FFT -> fused (fwd col, Wiener, inv col) -> inv row
    k_row_fwd_real<<<dim3(1024, imgs), 256>>>(y);
    k_col<1><<<dim3(256, imgs), 256>>>();
    k_row_inv_out<<<dim3(1024, imgs), 256>>>(out);
}

// round 2
// speedup vs baseline: 2.6665x; 2.6665x over previous
#include <cuda_runtime.h>
#include <math.h>

// BM3D-deblurring: RI filter + global empirical Wiener, in Fourier domain.
// v2: real-pair packing (2 images per complex FFT), radix-4 DIF/DIT with no
// bit-reversal passes, row-fused Wiener kernel with conjugate-mirror row pairs.

#define MAXPLANES 12
#define INVN  (1.0f / 1048576.0f)

static __device__ float2 g_Z[(size_t)MAXPLANES << 20]; // 96 MB packed spectra
static __device__ float2 g_P[1u << 20];                // OTF scratch
static __device__ float2 g_RI[1u << 20];               // RI filter (stored layout)
static __device__ float  g_PSD[1u << 20];              // colored-noise PSD
static __device__ float2 g_tw[1024];                   // W_1024^k

__device__ __forceinline__ int dr4(int i) {            // base-4 digit reversal, 10 bits
    unsigned x = __brev((unsigned)i) >> 22;
    return (int)(((x & 0x155u) << 1) | ((x & 0x2AAu) >> 1));
}
__device__ __forceinline__ float2 cmul(float2 a, float2 b) {
    return make_float2(a.x * b.x - a.y * b.y, a.x * b.y + a.y * b.x);
}
__device__ __forceinline__ float2 cmulj(float2 a, float2 w) {   // a * conj(w)
    return make_float2(a.x * w.x + a.y * w.y, a.y * w.x - a.x * w.y);
}

// Radix-4 DIF stage (forward). sh = 2*stage, stage 0..4. Natural in -> digit-rev out.
__device__ __forceinline__ void dif4(float2* s, int j, int sh) {
    int q = 256 >> sh;
    int p = j & (q - 1);
    int base = ((j - p) << 2) + p;
    float2 x0 = s[base], x1 = s[base + q], x2 = s[base + 2 * q], x3 = s[base + 3 * q];
    float2 t0 = make_float2(x0.x + x2.x, x0.y + x2.y);
    float2 t1 = make_float2(x0.x - x2.x, x0.y - x2.y);
    float2 t2 = make_float2(x1.x + x3.x, x1.y + x3.y);
    float2 t3 = make_float2(x1.x - x3.x, x1.y - x3.y);
    float2 u0 = make_float2(t0.x + t2.x, t0.y + t2.y);
    float2 u1 = make_float2(t1.x + t3.y, t1.y - t3.x);   // t1 - i*t3
    float2 u2 = make_float2(t0.x - t2.x, t0.y - t2.y);
    float2 u3 = make_float2(t1.x - t3.y, t1.y + t3.x);   // t1 + i*t3
    int e = p << sh;
    s[base]         = u0;
    s[base + q]     = cmul(u1, g_tw[e]);
    s[base + 2 * q] = cmul(u2, g_tw[2 * e]);
    s[base + 3 * q] = cmul(u3, g_tw[3 * e]);
}

// Radix-4 DIT stage (inverse, conj twiddles). Digit-rev in -> natural out.
__device__ __forceinline__ void dit4(float2* s, int j, int sh) {
    int h = 1 << sh;
    int p = j & (h - 1);
    int base = ((j - p) << 2) + p;
    int e = p << (8 - sh);
    float2 x0 = s[base];
    float2 x1 = cmulj(s[base + h],     g_tw[e]);
    float2 x2 = cmulj(s[base + 2 * h], g_tw[2 * e]);
    float2 x3 = cmulj(s[base + 3 * h], g_tw[3 * e]);
    float2 t0 = make_float2(x0.x + x2.x, x0.y + x2.y);
    float2 t1 = make_float2(x0.x - x2.x, x0.y - x2.y);
    float2 t2 = make_float2(x1.x + x3.x, x1.y + x3.y);
    float2 t3 = make_float2(x1.x - x3.x, x1.y - x3.y);
    s[base]         = make_float2(t0.x + t2.x, t0.y + t2.y);
    s[base + h]     = make_float2(t1.x - t3.y, t1.y + t3.x);   // t1 + i*t3
    s[base + 2 * h] = make_float2(t0.x - t2.x, t0.y - t2.y);
    s[base + 3 * h] = make_float2(t1.x + t3.y, t1.y - t3.x);   // t1 - i*t3
}

// ---------------- init: twiddles + circularly-rolled PSF -----------------
__global__ void k_init(const float* __restrict__ psf, int kh) {
    int idx = blockIdx.x * 256 + threadIdx.x;
    int r = idx >> 10, c = idx & 1023;
    int i = (r + (kh >> 1)) & 1023;
    int j = (c + (kh >> 1)) & 1023;
    float v = (i < kh && j < kh) ? psf[i * kh + j] : 0.f;
    g_P[idx] = make_float2(v, 0.f);
    if (idx < 1024) {
        float sn, cs;
        sincospif(-(float)idx / 512.0f, &sn, &cs);   // exp(-2*pi*i*idx/1024)
        g_tw[idx] = make_float2(cs, sn);
    }
}

// ---------------- OTF pipeline: column DIF then row DIF on g_P -----------
__global__ void __launch_bounds__(256) k_colP() {
    __shared__ float2 sm[4][1032];
    int tid = threadIdx.x, c0 = blockIdx.x << 2;
    for (int l = tid; l < 4096; l += 256) {
        int c = l & 3, r = l >> 2;
        sm[c][r] = g_P[(r << 10) + c0 + c];
    }
    __syncthreads();
    #pragma unroll
    for (int sh = 0; sh <= 8; sh += 2) {
        #pragma unroll
        for (int c = 0; c < 4; ++c) dif4(sm[c], tid, sh);
        __syncthreads();
    }
    for (int l = tid; l < 4096; l += 256) {
        int c = l & 3, r = l >> 2;
        g_P[(r << 10) + c0 + c] = sm[c][r];
    }
}

__global__ void __launch_bounds__(256) k_rowP() {
    __shared__ float2 sm[1024];
    int tid = threadIdx.x;
    size_t base = (size_t)blockIdx.x << 10;
    for (int l = tid; l < 1024; l += 256) sm[l] = g_P[base + l];
    __syncthreads();
    #pragma unroll
    for (int sh = 0; sh <= 8; sh += 2) { dif4(sm, tid, sh); __syncthreads(); }
    for (int l = tid; l < 1024; l += 256) g_P[base + l] = sm[l];
}

__global__ void k_ri() {   // elementwise in stored (digit-reversed) layout
    int idx = blockIdx.x * 256 + threadIdx.x;
    float2 h = g_P[idx];
    float d = h.x * h.x + h.y * h.y + 0.0025f;
    float inv = 1.0f / d;
    float rx = h.x * inv, ry = -h.y * inv;
    g_RI[idx]  = make_float2(rx, ry);
    g_PSD[idx] = 0.0025f * (rx * rx + ry * ry) * 1048576.0f;
}

// ---------------- pass 1: pack two real images, column DIF ---------------
__global__ void __launch_bounds__(256) k_col_fwd(const float* __restrict__ y) {
    __shared__ float2 sm[4][1032];
    int tid = threadIdx.x, c0 = blockIdx.x << 2;
    size_t pb = (size_t)blockIdx.y << 20;
    const float* ya = y + (pb << 1);
    const float* yb = ya + (1u << 20);
    for (int l = tid; l < 4096; l += 256) {
        int c = l & 3, r = l >> 2;
        int gi = (r << 10) + c0 + c;
        sm[c][r] = make_float2(ya[gi], yb[gi]);
    }
    __syncthreads();
    #pragma unroll
    for (int sh = 0; sh <= 8; sh += 2) {
        #pragma unroll
        for (int c = 0; c < 4; ++c) dif4(sm[c], tid, sh);
        __syncthreads();
    }
    for (int l = tid; l < 4096; l += 256) {
        int c = l & 3, r = l >> 2;
        g_Z[pb + (r << 10) + c0 + c] = sm[c][r];   // row index = stored slot
    }
}

// ---------------- pass 2: row DIF + unpack/Wiener/repack + row DIT -------
__device__ __forceinline__ void wiener_pair(float2 z1, float2 z2, int gi,
                                            float2& v1, float2& v2) {
    // unpack two real-image spectra from packed spectrum + its mirror
    float2 za = make_float2(0.5f * (z1.x + z2.x), 0.5f * (z1.y - z2.y));
    float2 zb = make_float2(0.5f * (z1.y + z2.y), 0.5f * (z2.x - z1.x));
    float2 ri = g_RI[gi];
    float  pp = g_PSD[gi];
    float2 a  = cmul(za, ri);
    float2 b  = cmul(zb, ri);
    float Sa = fmaxf((a.x * a.x + a.y * a.y) * INVN - pp, 0.f);
    float Sb = fmaxf((b.x * b.x + b.y * b.y) * INVN - pp, 0.f);
    float wa = Sa / (Sa + pp + 1e-12f);
    float wb = Sb / (Sb + pp + 1e-12f);
    a.x *= wa; a.y *= wa; b.x *= wb; b.y *= wb;
    v1 = make_float2(a.x - b.y, a.y + b.x);          // repacked at (u,c)
    v2 = make_float2(a.x + b.y, b.x - a.y);          // repacked at mirror
}

__global__ void __launch_bounds__(256) k_row_fused() {
    __shared__ float2 sm[2][1026];
    int tid = threadIdx.x, b = blockIdx.x;
    size_t pb = (size_t)blockIdx.y << 20;
    bool self = (b == 0);
    int suA = self ? 0 : dr4(b);
    int suB = self ? 2 : dr4(1024 - b);              // dr4(512)=2: freqs {0,512}
    for (int l = tid; l < 2048; l += 256) {
        int rw = l >> 10, x = l & 1023;
        sm[rw][x] = g_Z[pb + ((size_t)(rw ? suB : suA) << 10) + x];
    }
    __syncthreads();
    #pragma unroll
    for (int sh = 0; sh <= 8; sh += 2) {
        dif4(sm[0], tid, sh);
        dif4(sm[1], tid, sh);
        __syncthreads();
    }
    if (!self) {
        for (int l = tid; l < 1024; l += 256) {
            int sc = l;
            int c   = dr4(sc);
            int smc = dr4((1024 - c) & 1023);
            float2 v1, v2;
            wiener_pair(sm[0][sc], sm[1][smc], (suA << 10) + sc, v1, v2);
            sm[0][sc]  = v1;
            sm[1][smc] = v2;
        }
    } else {
        for (int l = tid; l < 1026; l += 256) {      // 513 freq pairs per row
            int row = (l >= 513);
            int cf  = l - (row ? 513 : 0);
            int sc  = dr4(cf);
            int smc = dr4((1024 - cf) & 1023);
            float2 v1, v2;
            wiener_pair(sm[row][sc], sm[row][smc],
                        ((row ? suB : suA) << 10) + sc, v1, v2);
            sm[row][sc]  = v1;
            sm[row][smc] = v2;
        }
    }
    __syncthreads();
    #pragma unroll
    for (int sh = 0; sh <= 8; sh += 2) {
        dit4(sm[0], tid, sh);
        dit4(sm[1], tid, sh);
        __syncthreads();
    }
    for (int l = tid; l < 2048; l += 256) {
        int rw = l >> 10, x = l & 1023;
        g_Z[pb + ((size_t)(rw ? suB : suA) << 10) + x] = sm[rw][x];
    }
}

// ---------------- pass 3: column DIT + unpack real/imag -> two images ----
__global__ void __launch_bounds__(256) k_col_inv(float* __restrict__ out) {
    __shared__ float2 sm[4][1032];
    int tid = threadIdx.x, c0 = blockIdx.x << 2;
    size_t pb = (size_t)blockIdx.y << 20;
    float* oa = out + (pb << 1);
    float* ob = oa + (1u << 20);
    for (int l = tid; l < 4096; l += 256) {
        int c = l & 3, r = l >> 2;
        sm[c][r] = g_Z[pb + (r << 10) + c0 + c];
    }
    __syncthreads();
    #pragma unroll
    for (int sh = 0; sh <= 8; sh += 2) {
        #pragma unroll
        for (int c = 0; c < 4; ++c) dit4(sm[c], tid, sh);
        __syncthreads();
    }
    for (int l = tid; l < 4096; l += 256) {
        int c = l & 3, r = l >> 2;
        float2 v = sm[c][r];
        int gi = (r << 10) + c0 + c;
        oa[gi] = v.x * INVN;
        ob[gi] = v.y * INVN;
    }
}

extern "C" void kernel_launch(void* const* d_in, const int* in_sizes, int n_in,
                              void* d_out, int out_size) {
    const float* y   = (const float*)d_in[0];
    const float* psf = (const float*)d_in[1];
    float* out = (float*)d_out;

    int imgs = in_sizes[0] >> 20;                    // 24
    int planes = imgs >> 1;                          // 12 packed complex planes
    if (planes > MAXPLANES) planes = MAXPLANES;
    int kh = (int)lroundf(sqrtf((float)in_sizes[1]));  // 25

    // OTF -> RI + PSD (stored digit-reversed layout matching main pipeline)
    k_init<<<4096, 256>>>(psf, kh);
    k_colP<<<256, 256>>>();
    k_rowP<<<1024, 256>>>();
    k_ri<<<4096, 256>>>();

    // main: col DIF -> fused(row DIF, Wiener on mirror row pairs, row DIT) -> col DIT
    k_col_fwd<<<dim3(256, planes), 256>>>(y);
    k_row_fused<<<dim3(512, planes), 256>>>();
    k_col_inv<<<dim3(256, planes), 256>>>(out);
}

// round 3
// speedup vs baseline: 4.4252x; 1.6596x over previous
#include <cuda_runtime.h>
#include <math.h>

// BM3D-deblurring: RI filter + global empirical Wiener, Fourier domain.
// v3: 16-points-per-thread radix-4 FFT. Stages grouped A(q=256,64 local) ->
// one conflict-free SMEM exchange -> B(q=16,4 local) -> C(q=1 via shfl).
// Real-pair packing (2 images / complex plane); row-fused Wiener pass.

#define MAXPLANES 12
#define INVN (1.0f / 1048576.0f)
#define PHYS(p) ((p) + (((p) >> 6) << 2))   // pad 4 float2 per 64 -> conflict-free
#define FSTR 1092                           // per-FFT smem stride (float2)

static __device__ float2 g_Z[(size_t)MAXPLANES << 20]; // 96 MB packed spectra
static __device__ float2 g_P[1u << 20];                // OTF scratch
static __device__ float2 g_RI[1u << 20];               // RI filter (stored layout)
static __device__ float  g_PSD[1u << 20];              // colored-noise PSD
static __device__ float2 g_tw[1024];                   // W_1024^k

__device__ __forceinline__ int dr4(int i) {            // base-4 digit reversal
    unsigned x = __brev((unsigned)i) >> 22;
    return (int)(((x & 0x155u) << 1) | ((x & 0x2AAu) >> 1));
}
__device__ __forceinline__ float2 cadd(float2 a, float2 b){ return make_float2(a.x+b.x, a.y+b.y); }
__device__ __forceinline__ float2 csub(float2 a, float2 b){ return make_float2(a.x-b.x, a.y-b.y); }
__device__ __forceinline__ float2 cmul(float2 a, float2 b){ return make_float2(a.x*b.x-a.y*b.y, a.x*b.y+a.y*b.x); }
__device__ __forceinline__ float2 cmulj(float2 a, float2 w){ return make_float2(a.x*w.x+a.y*w.y, a.y*w.x-a.x*w.y); }

// radix-4 DIF butterfly, twiddles applied on output (tw[e], tw[2e], tw[3e])
__device__ __forceinline__ void bf_dif(float2&x0, float2&x1, float2&x2, float2&x3, int e) {
    float2 t0=cadd(x0,x2), t1=csub(x0,x2), t2=cadd(x1,x3), t3=csub(x1,x3);
    float2 u1=make_float2(t1.x+t3.y, t1.y-t3.x);       // t1 - i t3
    float2 u3=make_float2(t1.x-t3.y, t1.y+t3.x);       // t1 + i t3
    x0=cadd(t0,t2);
    float2 u2=csub(t0,t2);
    x1=cmul(u1,g_tw[e]); x2=cmul(u2,g_tw[2*e]); x3=cmul(u3,g_tw[3*e]);
}
// radix-4 DIT butterfly, conj twiddles applied on input
__device__ __forceinline__ void bf_dit(float2&x0, float2&x1, float2&x2, float2&x3, int e) {
    float2 a1=cmulj(x1,g_tw[e]), a2=cmulj(x2,g_tw[2*e]), a3=cmulj(x3,g_tw[3*e]);
    float2 t0=cadd(x0,a2), t1=csub(x0,a2), t2=cadd(a1,a3), t3=csub(a1,a3);
    x0=cadd(t0,t2);
    x1=make_float2(t1.x-t3.y, t1.y+t3.x);              // t1 + i t3
    x2=csub(t0,t2);
    x3=make_float2(t1.x+t3.y, t1.y-t3.x);              // t1 - i t3
}

// Phase A (DIF): stages q=256, q=64 on x[k] <-> pos t+64k
__device__ __forceinline__ void dif_A(float2* x, int t) {
    #pragma unroll
    for (int k0=0;k0<4;k0++) bf_dif(x[k0],x[k0+4],x[k0+8],x[k0+12], t+64*k0);
    #pragma unroll
    for (int k0=0;k0<16;k0+=4) bf_dif(x[k0],x[k0+1],x[k0+2],x[k0+3], 4*t);
}
// Phase B (DIF): stages q=16, q=4 on x[4a+b] <-> pos 64m+16a+4b+e
__device__ __forceinline__ void dif_B(float2* x, int e) {
    #pragma unroll
    for (int b=0;b<4;b++) bf_dif(x[b],x[4+b],x[8+b],x[12+b], (4*b+e)<<4);
    #pragma unroll
    for (int a=0;a<4;a++) bf_dif(x[4*a],x[4*a+1],x[4*a+2],x[4*a+3], e<<6);
}
// Phase B (DIT): stages h=4, h=16 (ownership residue = eh)
__device__ __forceinline__ void dit_B(float2* x, int eh) {
    #pragma unroll
    for (int a=0;a<4;a++) bf_dit(x[4*a],x[4*a+1],x[4*a+2],x[4*a+3], eh<<6);
    #pragma unroll
    for (int b=0;b<4;b++) bf_dit(x[b],x[4+b],x[8+b],x[12+b], (4*b+eh)<<4);
}
// Phase A (DIT): stages h=64, h=256
__device__ __forceinline__ void dit_A(float2* x, int t) {
    #pragma unroll
    for (int k0=0;k0<16;k0+=4) bf_dit(x[k0],x[k0+1],x[k0+2],x[k0+3], t<<2);
    #pragma unroll
    for (int k0=0;k0<4;k0++) bf_dit(x[k0],x[k0+4],x[k0+8],x[k0+12], t+64*k0);
}

__device__ __forceinline__ float2 shx(float2 v, int m) {
    return make_float2(__shfl_xor_sync(0xffffffffu, v.x, m),
                       __shfl_xor_sync(0xffffffffu, v.y, m));
}
// Phase C (q=1/h=1) across the e-quad via shfl. Result belongs at pos G+perm[e],
// perm = {0,2,1,3} (= 2-bit reverse of e).
template <int M1, int M2>
__device__ __forceinline__ float2 difC(float2 v, int e) {
    float2 p = shx(v, M2);
    float2 A = ((e & 2) == 0) ? cadd(v, p) : csub(p, v);
    float2 q = shx(A, M1);
    if (e == 0) return cadd(A, q);
    if (e == 1) return csub(q, A);
    if (e == 2) return make_float2(A.x + q.y, A.y - q.x);   // A - i q
    return make_float2(q.x - A.y, q.y + A.x);               // q + i A
}
template <int M1, int M2>
__device__ __forceinline__ float2 ditC(float2 v, int e) {
    float2 p = shx(v, M2);
    float2 A = ((e & 2) == 0) ? cadd(v, p) : csub(p, v);
    float2 q = shx(A, M1);
    if (e == 0) return cadd(A, q);
    if (e == 1) return csub(q, A);
    if (e == 2) return make_float2(A.x - q.y, A.y + q.x);   // A + i q
    return make_float2(q.x + A.y, q.y - A.x);               // q - i A
}

// ---------------- init: twiddles + circularly-rolled PSF -----------------
__global__ void k_init(const float* __restrict__ psf, int kh) {
    int idx = blockIdx.x * 256 + threadIdx.x;
    int r = idx >> 10, c = idx & 1023;
    int i = (r + (kh >> 1)) & 1023;
    int j = (c + (kh >> 1)) & 1023;
    float v = (i < kh && j < kh) ? psf[i * kh + j] : 0.f;
    g_P[idx] = make_float2(v, 0.f);
    if (idx < 1024) {
        float sn, cs;
        sincospif(-(float)idx / 512.0f, &sn, &cs);
        g_tw[idx] = make_float2(cs, sn);
    }
}

// Legacy radix-4 DIF stage for the tiny PSF prep kernels.
__device__ __forceinline__ void dif4(float2* s, int j, int sh) {
    int q = 256 >> sh;
    int p = j & (q - 1);
    int base = ((j - p) << 2) + p;
    float2 x0=s[base], x1=s[base+q], x2=s[base+2*q], x3=s[base+3*q];
    float2 t0=cadd(x0,x2), t1=csub(x0,x2), t2=cadd(x1,x3), t3=csub(x1,x3);
    float2 u1=make_float2(t1.x+t3.y, t1.y-t3.x);
    float2 u3=make_float2(t1.x-t3.y, t1.y+t3.x);
    int e = p << sh;
    s[base]       = cadd(t0,t2);
    s[base+q]     = cmul(u1, g_tw[e]);
    s[base+2*q]   = cmul(csub(t0,t2), g_tw[2*e]);
    s[base+3*q]   = cmul(u3, g_tw[3*e]);
}

__global__ void __launch_bounds__(256) k_colP() {
    __shared__ float2 sm[4][1032];
    int tid = threadIdx.x, c0 = blockIdx.x << 2;
    for (int l = tid; l < 4096; l += 256) { int c=l&3, r=l>>2; sm[c][r]=g_P[(r<<10)+c0+c]; }
    __syncthreads();
    #pragma unroll
    for (int sh=0; sh<=8; sh+=2) {
        #pragma unroll
        for (int c=0;c<4;c++) dif4(sm[c], tid, sh);
        __syncthreads();
    }
    for (int l = tid; l < 4096; l += 256) { int c=l&3, r=l>>2; g_P[(r<<10)+c0+c]=sm[c][r]; }
}

// row DIF on OTF + fused RI/PSD computation (replaces separate k_ri)
__global__ void __launch_bounds__(256) k_rowP_ri() {
    __shared__ float2 sm[1024];
    int tid = threadIdx.x;
    size_t base = (size_t)blockIdx.x << 10;
    for (int l = tid; l < 1024; l += 256) sm[l] = g_P[base + l];
    __syncthreads();
    #pragma unroll
    for (int sh=0; sh<=8; sh+=2) { dif4(sm, tid, sh); __syncthreads(); }
    for (int l = tid; l < 1024; l += 256) {
        float2 h = sm[l];
        float d = h.x*h.x + h.y*h.y + 0.0025f;
        float inv = 1.0f / d;
        float rx = h.x*inv, ry = -h.y*inv;
        g_RI[base + l]  = make_float2(rx, ry);
        g_PSD[base + l] = 0.0025f * (rx*rx + ry*ry) * 1048576.0f;
    }
}

// ---------------- Wiener on a conjugate-mirror pair ----------------------
__device__ __forceinline__ void wiener_pair(float2 z1, float2 z2, int gi,
                                            float2& v1, float2& v2) {
    float2 za = make_float2(0.5f*(z1.x+z2.x), 0.5f*(z1.y-z2.y));
    float2 zb = make_float2(0.5f*(z1.y+z2.y), 0.5f*(z2.x-z1.x));
    float2 ri = g_RI[gi];
    float  pp = g_PSD[gi];
    float2 a = cmul(za, ri);
    float2 b = cmul(zb, ri);
    float Sa = fmaxf((a.x*a.x + a.y*a.y)*INVN - pp, 0.f);
    float Sb = fmaxf((b.x*b.x + b.y*b.y)*INVN - pp, 0.f);
    float wa = Sa / (Sa + pp + 1e-12f);
    float wb = Sb / (Sb + pp + 1e-12f);
    a.x*=wa; a.y*=wa; b.x*=wb; b.y*=wb;
    v1 = make_float2(a.x - b.y, a.y + b.x);
    v2 = make_float2(a.x + b.y, b.x - a.y);
}

__device__ __forceinline__ int rowof(int bx, int w, int h) {
    int U = 2*bx + w;
    if (U == 0) return h ? 2 : 0;                       // freqs {0, 512}: dr4 = {0, 2}
    return dr4(h ? 1024 - U : U);
}

// ---------------- pass 1: pack two real images, column DIF ---------------
__global__ void __launch_bounds__(256) k_col_fwd(const float* __restrict__ y) {
    __shared__ float2 sb[4 * FSTR];
    int tid = threadIdx.x;
    int f = tid & 3, t = tid >> 2;
    int m = t >> 2, e = t & 3;
    size_t pb = (size_t)blockIdx.y << 20;
    const float* ya = y + (pb << 1);
    const float* yb = ya + (1u << 20);
    int c = (blockIdx.x << 2) + f;
    float2* buf = sb + f * FSTR;
    float2 x[16];
    #pragma unroll
    for (int k=0;k<16;k++){ int r=t+64*k; x[k]=make_float2(ya[(r<<10)+c], yb[(r<<10)+c]); }
    dif_A(x, t);
    #pragma unroll
    for (int k=0;k<16;k++) buf[PHYS(t+64*k)] = x[k];
    __syncthreads();
    #pragma unroll
    for (int j=0;j<16;j++){ int a=j>>2,b=j&3; x[j]=buf[PHYS(64*m+16*a+4*b+e)]; }
    dif_B(x, e);
    int pe = ((e & 1) << 1) | ((e >> 1) & 1);
    #pragma unroll
    for (int j=0;j<16;j++){
        int a=j>>2, b=j&3;
        float2 r = difC<4, 8>(x[j], e);
        g_Z[pb + ((size_t)(64*m+16*a+4*b+pe) << 10) + c] = r;
    }
}

// ---------------- pass 2: row DIF + Wiener(mirror pairs) + row DIT -------
__global__ void __launch_bounds__(256) k_row_fused() {
    __shared__ float2 sb[4 * FSTR];
    int tid = threadIdx.x;
    int f = tid >> 6, t = tid & 63;
    int m = t >> 2, e = t & 3;
    size_t pb = (size_t)blockIdx.y << 20;
    int bx = blockIdx.x;
    int row = rowof(bx, f >> 1, f & 1);
    float2* buf = sb + f * FSTR;
    size_t gbase = pb + ((size_t)row << 10);
    float2 x[16];
    #pragma unroll
    for (int k=0;k<16;k++) x[k] = g_Z[gbase + t + 64*k];
    dif_A(x, t);
    #pragma unroll
    for (int k=0;k<16;k++) buf[PHYS(t+64*k)] = x[k];
    __syncthreads();
    #pragma unroll
    for (int j=0;j<16;j++){ int a=j>>2,b=j&3; x[j]=buf[PHYS(64*m+16*a+4*b+e)]; }
    dif_B(x, e);
    __syncthreads();                                   // all U-reads done before C-writes
    int pe = ((e & 1) << 1) | ((e >> 1) & 1);
    #pragma unroll
    for (int j=0;j<16;j++){
        int a=j>>2, b=j&3;
        buf[PHYS(64*m+16*a+4*b+pe)] = difC<1, 2>(x[j], e);
    }
    __syncthreads();
    // ---- Wiener on conjugate-mirror row pairs ----
    for (int l = tid; l < 2048; l += 256) {
        int w = l >> 10, sc = l & 1023;
        if (bx == 0 && w == 0) continue;               // special unit handled below
        int cfr = dr4(sc), smc = dr4((1024 - cfr) & 1023);
        float2 v1, v2;
        int rA = rowof(bx, w, 0);
        wiener_pair(sb[(2*w)*FSTR + PHYS(sc)], sb[(2*w+1)*FSTR + PHYS(smc)],
                    (rA << 10) + sc, v1, v2);
        sb[(2*w)*FSTR + PHYS(sc)] = v1;
        sb[(2*w+1)*FSTR + PHYS(smc)] = v2;
    }
    if (bx == 0) {                                     // rows freq 0 and 512: self-mirrored
        for (int l = tid; l < 1026; l += 256) {
            int rw = (l >= 513); int cf = l - 513 * rw;
            int sc = dr4(cf), smc = dr4((1024 - cf) & 1023);
            float2 v1, v2;
            int rA = rw ? 2 : 0;
            wiener_pair(sb[rw*FSTR + PHYS(sc)], sb[rw*FSTR + PHYS(smc)],
                        (rA << 10) + sc, v1, v2);
            sb[rw*FSTR + PHYS(sc)]  = v1;
            sb[rw*FSTR + PHYS(smc)] = v2;
        }
    }
    __syncthreads();
    // ---- inverse row FFT ----
    #pragma unroll
    for (int j=0;j<16;j++){
        int a=j>>2, b=j&3;
        float2 v = buf[PHYS(64*m+16*a+4*b+e)];
        x[j] = ditC<1, 2>(v, e);
    }
    dit_B(x, pe);
    __syncthreads();                                   // all C-reads done before exch writes
    #pragma unroll
    for (int j=0;j<16;j++){ int a=j>>2,b=j&3; buf[PHYS(64*m+16*a+4*b+pe)] = x[j]; }
    __syncthreads();
    #pragma unroll
    for (int k=0;k<16;k++) x[k] = buf[PHYS(t+64*k)];
    dit_A(x, t);
    #pragma unroll
    for (int k=0;k<16;k++) g_Z[gbase + t + 64*k] = x[k];
}

// ---------------- pass 3: column DIT + unpack real/imag ------------------
__global__ void __launch_bounds__(256) k_col_inv(float* __restrict__ out) {
    __shared__ float2 sb[4 * FSTR];
    int tid = threadIdx.x;
    int f = tid & 3, t = tid >> 2;
    int m = t >> 2, e = t & 3;
    size_t pb = (size_t)blockIdx.y << 20;
    float* oa = out + (pb << 1);
    float* ob = oa + (1u << 20);
    int c = (blockIdx.x << 2) + f;
    float2* buf = sb + f * FSTR;
    float2 x[16];
    #pragma unroll
    for (int j=0;j<16;j++){
        int a=j>>2, b=j&3;
        float2 v = g_Z[pb + ((size_t)(64*m+16*a+4*b+e) << 10) + c];
        x[j] = ditC<4, 8>(v, e);
    }
    int pe = ((e & 1) << 1) | ((e >> 1) & 1);
    dit_B(x, pe);
    #pragma unroll
    for (int j=0;j<16;j++){ int a=j>>2,b=j&3; buf[PHYS(64*m+16*a+4*b+pe)] = x[j]; }
    __syncthreads();
    #pragma unroll
    for (int k=0;k<16;k++) x[k] = buf[PHYS(t+64*k)];
    dit_A(x, t);
    #pragma unroll
    for (int k=0;k<16;k++){
        int r = t + 64*k;
        oa[(r<<10)+c] = x[k].x * INVN;
        ob[(r<<10)+c] = x[k].y * INVN;
    }
}

extern "C" void kernel_launch(void* const* d_in, const int* in_sizes, int n_in,
                              void* d_out, int out_size) {
    const float* y   = (const float*)d_in[0];
    const float* psf = (const float*)d_in[1];
    float* out = (float*)d_out;

    int imgs = in_sizes[0] >> 20;                      // 24
    int planes = imgs >> 1;                            // 12 packed complex planes
    if (planes > MAXPLANES) planes = MAXPLANES;
    int kh = (int)lroundf(sqrtf((float)in_sizes[1])); // 25

    // OTF -> RI + PSD (stored digit-reversed layout matching main pipeline)
    k_init<<<4096, 256>>>(psf, kh);
    k_colP<<<256, 256>>>();
    k_rowP_ri<<<1024, 256>>>();

    // main: col DIF -> fused(row DIF, Wiener, row DIT) -> col DIT
    k_col_fwd<<<dim3(256, planes), 256>>>(y);
    k_row_fused<<<dim3(256, planes), 256>>>();
    k_col_inv<<<dim3(256, planes), 256>>>(out);
}

// round 4
// speedup vs baseline: 4.9943x; 1.1286x over previous
#include <cuda_runtime.h>
#include <math.h>

// BM3D-deblurring: RI filter + global empirical Wiener, Fourier domain.
// v4: column passes widened to 8 columns/block (512 thr, 8 FFTs) so the real
// y/out accesses are full-sector coalesced; SMEM padding re-derived for 8-way
// conflict freedom (FSTR=1090). Row-fused Wiener pass unchanged.

#define MAXPLANES 12
#define INVN (1.0f / 1048576.0f)
#define PHYS(p) ((p) + (((p) >> 6) << 2))   // pad 4 float2 per 64
#define FSTR 1090                           // per-FFT smem stride; 2*FSTR%32==4

static __device__ float2 g_Z[(size_t)MAXPLANES << 20]; // 96 MB packed spectra
static __device__ float2 g_P[1u << 20];                // OTF scratch
static __device__ float2 g_RI[1u << 20];               // RI filter (stored layout)
static __device__ float  g_PSD[1u << 20];              // colored-noise PSD
static __device__ float2 g_tw[1024];                   // W_1024^k

__device__ __forceinline__ int dr4(int i) {            // base-4 digit reversal
    unsigned x = __brev((unsigned)i) >> 22;
    return (int)(((x & 0x155u) << 1) | ((x & 0x2AAu) >> 1));
}
__device__ __forceinline__ float2 cadd(float2 a, float2 b){ return make_float2(a.x+b.x, a.y+b.y); }
__device__ __forceinline__ float2 csub(float2 a, float2 b){ return make_float2(a.x-b.x, a.y-b.y); }
__device__ __forceinline__ float2 cmul(float2 a, float2 b){ return make_float2(a.x*b.x-a.y*b.y, a.x*b.y+a.y*b.x); }
__device__ __forceinline__ float2 cmulj(float2 a, float2 w){ return make_float2(a.x*w.x+a.y*w.y, a.y*w.x-a.x*w.y); }

__device__ __forceinline__ void bf_dif(float2&x0, float2&x1, float2&x2, float2&x3, int e) {
    float2 t0=cadd(x0,x2), t1=csub(x0,x2), t2=cadd(x1,x3), t3=csub(x1,x3);
    float2 u1=make_float2(t1.x+t3.y, t1.y-t3.x);
    float2 u3=make_float2(t1.x-t3.y, t1.y+t3.x);
    x0=cadd(t0,t2);
    float2 u2=csub(t0,t2);
    x1=cmul(u1,g_tw[e]); x2=cmul(u2,g_tw[2*e]); x3=cmul(u3,g_tw[3*e]);
}
__device__ __forceinline__ void bf_dit(float2&x0, float2&x1, float2&x2, float2&x3, int e) {
    float2 a1=cmulj(x1,g_tw[e]), a2=cmulj(x2,g_tw[2*e]), a3=cmulj(x3,g_tw[3*e]);
    float2 t0=cadd(x0,a2), t1=csub(x0,a2), t2=cadd(a1,a3), t3=csub(a1,a3);
    x0=cadd(t0,t2);
    x1=make_float2(t1.x-t3.y, t1.y+t3.x);
    x2=csub(t0,t2);
    x3=make_float2(t1.x+t3.y, t1.y-t3.x);
}

__device__ __forceinline__ void dif_A(float2* x, int t) {
    #pragma unroll
    for (int k0=0;k0<4;k0++) bf_dif(x[k0],x[k0+4],x[k0+8],x[k0+12], t+64*k0);
    #pragma unroll
    for (int k0=0;k0<16;k0+=4) bf_dif(x[k0],x[k0+1],x[k0+2],x[k0+3], 4*t);
}
__device__ __forceinline__ void dif_B(float2* x, int e) {
    #pragma unroll
    for (int b=0;b<4;b++) bf_dif(x[b],x[4+b],x[8+b],x[12+b], (4*b+e)<<4);
    #pragma unroll
    for (int a=0;a<4;a++) bf_dif(x[4*a],x[4*a+1],x[4*a+2],x[4*a+3], e<<6);
}
__device__ __forceinline__ void dit_B(float2* x, int eh) {
    #pragma unroll
    for (int a=0;a<4;a++) bf_dit(x[4*a],x[4*a+1],x[4*a+2],x[4*a+3], eh<<6);
    #pragma unroll
    for (int b=0;b<4;b++) bf_dit(x[b],x[4+b],x[8+b],x[12+b], (4*b+eh)<<4);
}
__device__ __forceinline__ void dit_A(float2* x, int t) {
    #pragma unroll
    for (int k0=0;k0<16;k0+=4) bf_dit(x[k0],x[k0+1],x[k0+2],x[k0+3], t<<2);
    #pragma unroll
    for (int k0=0;k0<4;k0++) bf_dit(x[k0],x[k0+4],x[k0+8],x[k0+12], t+64*k0);
}

__device__ __forceinline__ float2 shx(float2 v, int m) {
    return make_float2(__shfl_xor_sync(0xffffffffu, v.x, m),
                       __shfl_xor_sync(0xffffffffu, v.y, m));
}
template <int M1, int M2>
__device__ __forceinline__ float2 difC(float2 v, int e) {
    float2 p = shx(v, M2);
    float2 A = ((e & 2) == 0) ? cadd(v, p) : csub(p, v);
    float2 q = shx(A, M1);
    if (e == 0) return cadd(A, q);
    if (e == 1) return csub(q, A);
    if (e == 2) return make_float2(A.x + q.y, A.y - q.x);
    return make_float2(q.x - A.y, q.y + A.x);
}
template <int M1, int M2>
__device__ __forceinline__ float2 ditC(float2 v, int e) {
    float2 p = shx(v, M2);
    float2 A = ((e & 2) == 0) ? cadd(v, p) : csub(p, v);
    float2 q = shx(A, M1);
    if (e == 0) return cadd(A, q);
    if (e == 1) return csub(q, A);
    if (e == 2) return make_float2(A.x - q.y, A.y + q.x);
    return make_float2(q.x + A.y, q.y - A.x);
}

// ---------------- init: twiddles + circularly-rolled PSF -----------------
__global__ void k_init(const float* __restrict__ psf, int kh) {
    int idx = blockIdx.x * 256 + threadIdx.x;
    int r = idx >> 10, c = idx & 1023;
    int i = (r + (kh >> 1)) & 1023;
    int j = (c + (kh >> 1)) & 1023;
    float v = (i < kh && j < kh) ? psf[i * kh + j] : 0.f;
    g_P[idx] = make_float2(v, 0.f);
    if (idx < 1024) {
        float sn, cs;
        sincospif(-(float)idx / 512.0f, &sn, &cs);
        g_tw[idx] = make_float2(cs, sn);
    }
}

// Legacy radix-4 DIF stage for the tiny PSF prep kernels.
__device__ __forceinline__ void dif4(float2* s, int j, int sh) {
    int q = 256 >> sh;
    int p = j & (q - 1);
    int base = ((j - p) << 2) + p;
    float2 x0=s[base], x1=s[base+q], x2=s[base+2*q], x3=s[base+3*q];
    float2 t0=cadd(x0,x2), t1=csub(x0,x2), t2=cadd(x1,x3), t3=csub(x1,x3);
    float2 u1=make_float2(t1.x+t3.y, t1.y-t3.x);
    float2 u3=make_float2(t1.x-t3.y, t1.y+t3.x);
    int e = p << sh;
    s[base]       = cadd(t0,t2);
    s[base+q]     = cmul(u1, g_tw[e]);
    s[base+2*q]   = cmul(csub(t0,t2), g_tw[2*e]);
    s[base+3*q]   = cmul(u3, g_tw[3*e]);
}

__global__ void __launch_bounds__(256) k_colP() {
    __shared__ float2 sm[4][1032];
    int tid = threadIdx.x, c0 = blockIdx.x << 2;
    for (int l = tid; l < 4096; l += 256) { int c=l&3, r=l>>2; sm[c][r]=g_P[(r<<10)+c0+c]; }
    __syncthreads();
    #pragma unroll
    for (int sh=0; sh<=8; sh+=2) {
        #pragma unroll
        for (int c=0;c<4;c++) dif4(sm[c], tid, sh);
        __syncthreads();
    }
    for (int l = tid; l < 4096; l += 256) { int c=l&3, r=l>>2; g_P[(r<<10)+c0+c]=sm[c][r]; }
}

__global__ void __launch_bounds__(256) k_rowP_ri() {
    __shared__ float2 sm[1024];
    int tid = threadIdx.x;
    size_t base = (size_t)blockIdx.x << 10;
    for (int l = tid; l < 1024; l += 256) sm[l] = g_P[base + l];
    __syncthreads();
    #pragma unroll
    for (int sh=0; sh<=8; sh+=2) { dif4(sm, tid, sh); __syncthreads(); }
    for (int l = tid; l < 1024; l += 256) {
        float2 h = sm[l];
        float d = h.x*h.x + h.y*h.y + 0.0025f;
        float inv = 1.0f / d;
        float rx = h.x*inv, ry = -h.y*inv;
        g_RI[base + l]  = make_float2(rx, ry);
        g_PSD[base + l] = 0.0025f * (rx*rx + ry*ry) * 1048576.0f;
    }
}

// ---------------- Wiener on a conjugate-mirror pair ----------------------
__device__ __forceinline__ void wiener_pair(float2 z1, float2 z2, int gi,
                                            float2& v1, float2& v2) {
    float2 za = make_float2(0.5f*(z1.x+z2.x), 0.5f*(z1.y-z2.y));
    float2 zb = make_float2(0.5f*(z1.y+z2.y), 0.5f*(z2.x-z1.x));
    float2 ri = g_RI[gi];
    float  pp = g_PSD[gi];
    float2 a = cmul(za, ri);
    float2 b = cmul(zb, ri);
    float Sa = fmaxf((a.x*a.x + a.y*a.y)*INVN - pp, 0.f);
    float Sb = fmaxf((b.x*b.x + b.y*b.y)*INVN - pp, 0.f);
    float wa = Sa / (Sa + pp + 1e-12f);
    float wb = Sb / (Sb + pp + 1e-12f);
    a.x*=wa; a.y*=wa; b.x*=wb; b.y*=wb;
    v1 = make_float2(a.x - b.y, a.y + b.x);
    v2 = make_float2(a.x + b.y, b.x - a.y);
}

__device__ __forceinline__ int rowof(int bx, int w, int h) {
    int U = 2*bx + w;
    if (U == 0) return h ? 2 : 0;                       // freqs {0,512}: dr4={0,2}
    return dr4(h ? 1024 - U : U);
}

// ---------------- pass 1: pack two real images, column DIF (8 cols) -----
__global__ void __launch_bounds__(512) k_col_fwd(const float* __restrict__ y) {
    extern __shared__ float2 sb[];
    int tid = threadIdx.x;
    int f = tid & 7, t = tid >> 3;           // 8 FFT slots, 64 threads each
    int m = t >> 2, e = t & 3;
    size_t pb = (size_t)blockIdx.y << 20;
    const float* ya = y + (pb << 1);
    const float* yb = ya + (1u << 20);
    int c = (blockIdx.x << 3) + f;
    float2* buf = sb + f * FSTR;
    float2 x[16];
    #pragma unroll
    for (int k=0;k<16;k++){ int r=t+64*k; x[k]=make_float2(ya[(r<<10)+c], yb[(r<<10)+c]); }
    dif_A(x, t);
    #pragma unroll
    for (int k=0;k<16;k++) buf[PHYS(t+64*k)] = x[k];
    __syncthreads();
    #pragma unroll
    for (int j=0;j<16;j++){ int a=j>>2,b=j&3; x[j]=buf[PHYS(64*m+16*a+4*b+e)]; }
    dif_B(x, e);
    int pe = ((e & 1) << 1) | ((e >> 1) & 1);
    #pragma unroll
    for (int j=0;j<16;j++){
        int a=j>>2, b=j&3;
        float2 r = difC<8, 16>(x[j], e);
        g_Z[pb + ((size_t)(64*m+16*a+4*b+pe) << 10) + c] = r;
    }
}

// ---------------- pass 2: row DIF + Wiener(mirror pairs) + row DIT -------
__global__ void __launch_bounds__(256) k_row_fused() {
    __shared__ float2 sb[4 * FSTR];
    int tid = threadIdx.x;
    int f = tid >> 6, t = tid & 63;
    int m = t >> 2, e = t & 3;
    size_t pb = (size_t)blockIdx.y << 20;
    int bx = blockIdx.x;
    int row = rowof(bx, f >> 1, f & 1);
    float2* buf = sb + f * FSTR;
    size_t gbase = pb + ((size_t)row << 10);
    float2 x[16];
    #pragma unroll
    for (int k=0;k<16;k++) x[k] = g_Z[gbase + t + 64*k];
    dif_A(x, t);
    #pragma unroll
    for (int k=0;k<16;k++) buf[PHYS(t+64*k)] = x[k];
    __syncthreads();
    #pragma unroll
    for (int j=0;j<16;j++){ int a=j>>2,b=j&3; x[j]=buf[PHYS(64*m+16*a+4*b+e)]; }
    dif_B(x, e);
    __syncthreads();
    int pe = ((e & 1) << 1) | ((e >> 1) & 1);
    #pragma unroll
    for (int j=0;j<16;j++){
        int a=j>>2, b=j&3;
        buf[PHYS(64*m+16*a+4*b+pe)] = difC<1, 2>(x[j], e);
    }
    __syncthreads();
    for (int l = tid; l < 2048; l += 256) {
        int w = l >> 10, sc = l & 1023;
        if (bx == 0 && w == 0) continue;
        int cfr = dr4(sc), smc = dr4((1024 - cfr) & 1023);
        float2 v1, v2;
        int rA = rowof(bx, w, 0);
        wiener_pair(sb[(2*w)*FSTR + PHYS(sc)], sb[(2*w+1)*FSTR + PHYS(smc)],
                    (rA << 10) + sc, v1, v2);
        sb[(2*w)*FSTR + PHYS(sc)] = v1;
        sb[(2*w+1)*FSTR + PHYS(smc)] = v2;
    }
    if (bx == 0) {
        for (int l = tid; l < 1026; l += 256) {
            int rw = (l >= 513); int cf = l - 513 * rw;
            int sc = dr4(cf), smc = dr4((1024 - cf) & 1023);
            float2 v1, v2;
            int rA = rw ? 2 : 0;
            wiener_pair(sb[rw*FSTR + PHYS(sc)], sb[rw*FSTR + PHYS(smc)],
                        (rA << 10) + sc, v1, v2);
            sb[rw*FSTR + PHYS(sc)]  = v1;
            sb[rw*FSTR + PHYS(smc)] = v2;
        }
    }
    __syncthreads();
    #pragma unroll
    for (int j=0;j<16;j++){
        int a=j>>2, b=j&3;
        float2 v = buf[PHYS(64*m+16*a+4*b+e)];
        x[j] = ditC<1, 2>(v, e);
    }
    dit_B(x, pe);
    __syncthreads();
    #pragma unroll
    for (int j=0;j<16;j++){ int a=j>>2,b=j&3; buf[PHYS(64*m+16*a+4*b+pe)] = x[j]; }
    __syncthreads();
    #pragma unroll
    for (int k=0;k<16;k++) x[k] = buf[PHYS(t+64*k)];
    dit_A(x, t);
    #pragma unroll
    for (int k=0;k<16;k++) g_Z[gbase + t + 64*k] = x[k];
}

// ---------------- pass 3: column DIT + unpack real/imag (8 cols) --------
__global__ void __launch_bounds__(512) k_col_inv(float* __restrict__ out) {
    extern __shared__ float2 sb[];
    int tid = threadIdx.x;
    int f = tid & 7, t = tid >> 3;
    int m = t >> 2, e = t & 3;
    size_t pb = (size_t)blockIdx.y << 20;
    float* oa = out + (pb << 1);
    float* ob = oa + (1u << 20);
    int c = (blockIdx.x << 3) + f;
    float2* buf = sb + f * FSTR;
    float2 x[16];
    #pragma unroll
    for (int j=0;j<16;j++){
        int a=j>>2, b=j&3;
        float2 v = g_Z[pb + ((size_t)(64*m+16*a+4*b+e) << 10) + c];
        x[j] = ditC<8, 16>(v, e);
    }
    int pe = ((e & 1) << 1) | ((e >> 1) & 1);
    dit_B(x, pe);
    #pragma unroll
    for (int j=0;j<16;j++){ int a=j>>2,b=j&3; buf[PHYS(64*m+16*a+4*b+pe)] = x[j]; }
    __syncthreads();
    #pragma unroll
    for (int k=0;k<16;k++) x[k] = buf[PHYS(t+64*k)];
    dit_A(x, t);
    #pragma unroll
    for (int k=0;k<16;k++){
        int r = t + 64*k;
        oa[(r<<10)+c] = x[k].x * INVN;
        ob[(r<<10)+c] = x[k].y * INVN;
    }
}

extern "C" void kernel_launch(void* const* d_in, const int* in_sizes, int n_in,
                              void* d_out, int out_size) {
    const float* y   = (const float*)d_in[0];
    const float* psf = (const float*)d_in[1];
    float* out = (float*)d_out;

    int imgs = in_sizes[0] >> 20;                      // 24
    int planes = imgs >> 1;                            // 12 packed complex planes
    if (planes > MAXPLANES) planes = MAXPLANES;
    int kh = (int)lroundf(sqrtf((float)in_sizes[1])); // 25

    const int colSmem = 8 * FSTR * (int)sizeof(float2);   // ~68 KB dynamic
    cudaFuncSetAttribute(k_col_fwd, cudaFuncAttributeMaxDynamicSharedMemorySize, colSmem);
    cudaFuncSetAttribute(k_col_inv, cudaFuncAttributeMaxDynamicSharedMemorySize, colSmem);

    // OTF -> RI + PSD (stored digit-reversed layout matching main pipeline)
    k_init<<<4096, 256>>>(psf, kh);
    k_colP<<<256, 256>>>();
    k_rowP_ri<<<1024, 256>>>();

    // main: col DIF -> fused(row DIF, Wiener, row DIT) -> col DIT
    k_col_fwd<<<dim3(128, planes), 512, colSmem>>>(y);
    k_row_fused<<<dim3(256, planes), 256>>>();
    k_col_inv<<<dim3(128, planes), 512, colSmem>>>(out);
}